// round 1
// baseline (speedup 1.0000x reference)
#include <cuda_runtime.h>
#include <math.h>

// Problem constants
#define B_  2
#define S_  4096
#define HID_ 1024
#define H_  16
#define D_  64
#define M_  (B_*S_)        // 8192 rows
#define N1_ (3*H_*D_)      // 3072
#define N2_ HID_           // 1024
#define K_  HID_           // 1024

// Scratch (no cudaMalloc allowed)
__device__ float g_mixed[(size_t)M_*K_];     //  33.5 MB
__device__ float g_rkv[(size_t)M_*N1_];      // 100.7 MB
__device__ float g_r[(size_t)M_*HID_];       //  33.5 MB
__device__ float g_kv[(size_t)M_*HID_];      //  33.5 MB
__device__ float g_att[(size_t)M_*HID_];     //  33.5 MB
__device__ float g_gfac;                     // e^{-avg_decay}

// ---------------------------------------------------------------------------
// 1) token mix: mixed = h*tm + shift(h)*(1-tm)
// ---------------------------------------------------------------------------
__global__ void mix_kernel(const float* __restrict__ h,
                           const float* __restrict__ tm) {
    int i4 = blockIdx.x * blockDim.x + threadIdx.x;        // float4 index
    const int TOT4 = (M_ * HID_) / 4;
    if (i4 >= TOT4) return;
    int idx = i4 * 4;
    int c   = idx & (HID_ - 1);
    int bs  = idx >> 10;            // /HID_
    int s   = bs & (S_ - 1);
    float4 hv = *(const float4*)(h + idx);
    float4 tv = *(const float4*)(tm + c);
    float4 pv = make_float4(0.f, 0.f, 0.f, 0.f);
    if (s != 0) pv = *(const float4*)(h + idx - HID_);
    float4 o;
    o.x = hv.x * tv.x + pv.x * (1.f - tv.x);
    o.y = hv.y * tv.y + pv.y * (1.f - tv.y);
    o.z = hv.z * tv.z + pv.z * (1.f - tv.z);
    o.w = hv.w * tv.w + pv.w * (1.f - tv.w);
    *(float4*)(g_mixed + idx) = o;
}

// ---------------------------------------------------------------------------
// 2/6) SGEMM NT: C[M,N] = A[M,K] * B[N,K]^T   (both row-major, K contiguous)
//     128x128 tile, BK=16, 256 threads, 8x8 per thread.
// ---------------------------------------------------------------------------
#define BM 128
#define BN 128
#define BK 16
#define SPAD 4   // smem row padding to kill store conflicts

__global__ void __launch_bounds__(256, 2)
sgemm_nt(const float* __restrict__ A, const float* __restrict__ B,
         float* __restrict__ C, int M, int N, int K) {
    __shared__ float As[BK][BM + SPAD];
    __shared__ float Bs[BK][BN + SPAD];

    const int bm = blockIdx.y * BM;
    const int bn = blockIdx.x * BN;
    const int tid = threadIdx.x;
    const int tx = tid & 15;   // 0..15  -> 8 cols each
    const int ty = tid >> 4;   // 0..15  -> 8 rows each

    float acc[8][8];
    #pragma unroll
    for (int i = 0; i < 8; i++)
        #pragma unroll
        for (int j = 0; j < 8; j++) acc[i][j] = 0.f;

    for (int k0 = 0; k0 < K; k0 += BK) {
        // Each thread loads 2 float4 from A and 2 from B, stores transposed.
        #pragma unroll
        for (int i = 0; i < 2; i++) {
            int t   = tid + i * 256;       // 0..511
            int row = t >> 2;              // 0..127
            int kq  = (t & 3) * 4;         // 0,4,8,12
            float4 a = *(const float4*)(A + (size_t)(bm + row) * K + k0 + kq);
            As[kq + 0][row] = a.x; As[kq + 1][row] = a.y;
            As[kq + 2][row] = a.z; As[kq + 3][row] = a.w;
            float4 b = *(const float4*)(B + (size_t)(bn + row) * K + k0 + kq);
            Bs[kq + 0][row] = b.x; Bs[kq + 1][row] = b.y;
            Bs[kq + 2][row] = b.z; Bs[kq + 3][row] = b.w;
        }
        __syncthreads();

        #pragma unroll
        for (int kk = 0; kk < BK; kk++) {
            float ar[8], br[8];
            *(float4*)&ar[0] = *(const float4*)&As[kk][ty * 8];
            *(float4*)&ar[4] = *(const float4*)&As[kk][ty * 8 + 4];
            *(float4*)&br[0] = *(const float4*)&Bs[kk][tx * 8];
            *(float4*)&br[4] = *(const float4*)&Bs[kk][tx * 8 + 4];
            #pragma unroll
            for (int i = 0; i < 8; i++)
                #pragma unroll
                for (int j = 0; j < 8; j++)
                    acc[i][j] = fmaf(ar[i], br[j], acc[i][j]);
        }
        __syncthreads();
    }

    #pragma unroll
    for (int i = 0; i < 8; i++) {
        float* crow = C + (size_t)(bm + ty * 8 + i) * N + bn + tx * 8;
        *(float4*)(crow)     = *(float4*)&acc[i][0];
        *(float4*)(crow + 4) = *(float4*)&acc[i][4];
    }
}

// ---------------------------------------------------------------------------
// 3) sigmoid + RoPE + kv = k*v
//    rkv layout per row: [r(1024) | k(1024) | v(1024)], within each: h*64+d
// ---------------------------------------------------------------------------
__global__ void rope_kv_kernel(const float* __restrict__ cosb,
                               const float* __restrict__ sinb) {
    int idx = blockIdx.x * blockDim.x + threadIdx.x;   // over M_*HID_
    if (idx >= M_ * HID_) return;
    int d  = idx & 63;
    int hd = idx & (HID_ - 1);
    int bs = idx >> 10;
    int s  = bs & (S_ - 1);
    const float* base = g_rkv + (size_t)bs * N1_;
    int pd = hd ^ 32;                    // partner within the head

    float rv  = base[hd];
    float rpv = base[pd];
    float kv  = base[1024 + hd];
    float kpv = base[1024 + pd];
    float vv  = base[2048 + hd];

    float c  = cosb[s * 64 + d];
    float sn = sinb[s * 64 + d];
    float sign = (d < 32) ? -1.f : 1.f;

    float rs  = 1.f / (1.f + __expf(-rv));
    float rps = 1.f / (1.f + __expf(-rpv));
    float rr  = rs * c + sign * rps * sn;
    float kk  = kv * c + sign * kpv * sn;

    g_r[idx]  = rr;
    g_kv[idx] = kk * vv;
}

// ---------------------------------------------------------------------------
// 4) prep: g = exp(-avg_decay) = exp(mean(exp(time_decay)))
//    (avg_decay = mean(-exp(td)), so -avg_decay = mean(exp(td)))
// ---------------------------------------------------------------------------
__global__ void prep_kernel(const float* __restrict__ td) {
    __shared__ float red[256];
    float s = 0.f;
    for (int i = threadIdx.x; i < H_ * D_; i += 256) s += expf(td[i]);
    red[threadIdx.x] = s;
    __syncthreads();
    for (int w = 128; w > 0; w >>= 1) {
        if (threadIdx.x < w) red[threadIdx.x] += red[threadIdx.x + w];
        __syncthreads();
    }
    if (threadIdx.x == 0) g_gfac = expf(red[0] / (float)(H_ * D_));
}

// ---------------------------------------------------------------------------
// 5) backward scan (per channel) + output gate
//    U[i]   = kv[i] + g*U[i+1]
//    den[i] = 1     + g*den[i+1]
//    att[i] = r[i] * (time_first * kv[i] + U[i]/(den[i]+1e-8))
// ---------------------------------------------------------------------------
__global__ void scan_kernel(const float* __restrict__ tf) {
    int b = blockIdx.x >> 4;           // 0..1
    int h = blockIdx.x & 15;           // 0..15
    int d = threadIdx.x;               // 0..63
    float g   = g_gfac;
    float tfv = tf[h * 64 + d];
    size_t ch = (size_t)h * 64 + d;
    float u = 0.f, den = 0.f;
    size_t rowbase = ((size_t)b * S_ + (S_ - 1)) * HID_ + ch;
    #pragma unroll 4
    for (int i = S_ - 1; i >= 0; --i, rowbase -= HID_) {
        float kvv = g_kv[rowbase];
        u   = fmaf(g, u, kvv);
        den = fmaf(g, den, 1.f);
        float wkv = u / (den + 1e-8f);
        g_att[rowbase] = g_r[rowbase] * (tfv * kvv + wkv);
    }
}

// ---------------------------------------------------------------------------
// launch
// ---------------------------------------------------------------------------
extern "C" void kernel_launch(void* const* d_in, const int* in_sizes, int n_in,
                              void* d_out, int out_size) {
    const float* hidden = (const float*)d_in[0];
    const float* cosb   = (const float*)d_in[1];
    const float* sinb   = (const float*)d_in[2];
    const float* W_rkv  = (const float*)d_in[3];
    const float* W_o    = (const float*)d_in[4];
    const float* tdec   = (const float*)d_in[5];
    const float* tfirst = (const float*)d_in[6];
    const float* tmix   = (const float*)d_in[7];
    float* out = (float*)d_out;

    float* mixed; cudaGetSymbolAddress((void**)&mixed, g_mixed);
    float* rkv;   cudaGetSymbolAddress((void**)&rkv,   g_rkv);
    float* att;   cudaGetSymbolAddress((void**)&att,   g_att);

    // 1) token mix
    mix_kernel<<<(M_ * HID_ / 4 + 255) / 256, 256>>>(hidden, tmix);

    // 2) rkv = mixed @ W_rkv^T
    sgemm_nt<<<dim3(N1_ / BN, M_ / BM), 256>>>(mixed, W_rkv, rkv, M_, N1_, K_);

    // 3) sigmoid + rope + kv
    rope_kv_kernel<<<(M_ * HID_ + 255) / 256, 256>>>(cosb, sinb);

    // 4) scalar decay factor
    prep_kernel<<<1, 256>>>(tdec);

    // 5) backward scan + gate
    scan_kernel<<<B_ * H_, D_>>>(tfirst);

    // 6) out = att @ W_o^T
    sgemm_nt<<<dim3(N2_ / BN, M_ / BM), 256>>>(att, W_o, out, M_, N2_, K_);
}

// round 8
// speedup vs baseline: 5.8917x; 5.8917x over previous
#include <cuda_runtime.h>
#include <cuda_bf16.h>
#include <stdint.h>
#include <math.h>

// Problem constants
#define B_   2
#define S_   4096
#define HID_ 1024
#define H_   16
#define D_   64
#define M_   (B_*S_)        // 8192
#define N1_  (3*H_*D_)      // 3072
#define N2_  HID_           // 1024
#define K3   3072           // split-K': [ah|al|ah] x [bh|bh|bl]

// ---------------------------------------------------------------------------
// Scratch (no cudaMalloc allowed)
// ---------------------------------------------------------------------------
__device__ __align__(256) __nv_bfloat16 g_A2[(size_t)M_*K3];      // 50.3 MB
__device__ __align__(256) __nv_bfloat16 g_B2rkv[(size_t)N1_*K3];  // 18.9 MB
__device__ __align__(256) __nv_bfloat16 g_B2o[(size_t)N2_*K3];    //  6.3 MB
__device__ __align__(256) float g_rkv[(size_t)M_*N1_];            // 100.7 MB
__device__ __align__(256) float g_r[(size_t)M_*HID_];             //  33.5 MB
__device__ __align__(256) float g_kv[(size_t)M_*HID_];            //  33.5 MB
__device__ __align__(256) float g_uloc[(size_t)M_*HID_];          //  33.5 MB
__device__ __align__(256) float g_T[(size_t)B_*64*HID_];          //   0.5 MB
__device__ __align__(256) float g_carry[(size_t)B_*64*HID_];      //   0.5 MB
__device__ float g_gfac;   // exp(a)
__device__ float g_apos;   // a = mean(exp(time_decay)) = -avg_decay

// ---------------------------------------------------------------------------
// helpers
// ---------------------------------------------------------------------------
__device__ __forceinline__ uint32_t smem_u32(const void* p) {
    uint32_t a;
    asm("{ .reg .u64 t; cvta.to.shared.u64 t, %1; cvt.u32.u64 %0, t; }" : "=r"(a) : "l"(p));
    return a;
}
__device__ __forceinline__ void cp16(uint32_t dst, const void* src) {
    asm volatile("cp.async.cg.shared.global [%0], [%1], 16;" :: "r"(dst), "l"(src));
}
__device__ __forceinline__ void ldm_x4(uint32_t* r, uint32_t addr) {
    asm volatile("ldmatrix.sync.aligned.m8n8.x4.shared.b16 {%0,%1,%2,%3}, [%4];"
                 : "=r"(r[0]), "=r"(r[1]), "=r"(r[2]), "=r"(r[3]) : "r"(addr));
}
__device__ __forceinline__ void mma16816(float* c, const uint32_t* a, const uint32_t* b) {
    asm volatile(
        "mma.sync.aligned.m16n8k16.row.col.f32.bf16.bf16.f32 "
        "{%0,%1,%2,%3}, {%4,%5,%6,%7}, {%8,%9}, {%0,%1,%2,%3};"
        : "+f"(c[0]), "+f"(c[1]), "+f"(c[2]), "+f"(c[3])
        : "r"(a[0]), "r"(a[1]), "r"(a[2]), "r"(a[3]), "r"(b[0]), "r"(b[1]));
}

// ---------------------------------------------------------------------------
// bf16 HMMA GEMM: C[M,N] = A[M,K3] * B[N,K3]^T, fp32 out.
// CTA tile 128x128, BK=32, 2-stage cp.async double buffer, 8 warps.
// Per warp: 64x32 (4 m-frags x 4 n-frags of m16n8k16).
// ---------------------------------------------------------------------------
#define BK 32
#define NKT (K3/BK)          // 96
#define LDS_ (BK + 8)        // 40 elems (80B rows: 16B-aligned, ldmatrix conflict-free)
#define TILE_E (128*LDS_)    // elems per tile

__global__ void __launch_bounds__(256, 2)
gemm_hmma(const __nv_bfloat16* __restrict__ A,
          const __nv_bfloat16* __restrict__ Bm,
          float* __restrict__ C, int N) {
    __shared__ __nv_bfloat16 sA[2][TILE_E];
    __shared__ __nv_bfloat16 sB[2][TILE_E];

    const int tid = threadIdx.x;
    const int wid = tid >> 5, lane = tid & 31;
    const int bm = blockIdx.y * 128;
    const int bn = blockIdx.x * 128;
    const int wm = (wid & 1) * 64;    // warp m offset in tile
    const int wn = (wid >> 1) * 32;   // warp n offset in tile

    // cp.async assignment: 512 16B-chunks per tile, 2 per thread
    // chunk c: row=c>>2, kcol=(c&3)*8
    const int c0r = (tid) >> 2,        c0k = (tid & 3) * 8;
    const int c1r = (tid + 256) >> 2,  c1k = ((tid + 256) & 3) * 8;

    float acc[4][4][4];
    #pragma unroll
    for (int i = 0; i < 4; i++)
        #pragma unroll
        for (int j = 0; j < 4; j++)
            #pragma unroll
            for (int q = 0; q < 4; q++) acc[i][j][q] = 0.f;

    const uint32_t sAb = smem_u32(&sA[0][0]);
    const uint32_t sBb = smem_u32(&sB[0][0]);

    // ldmatrix lane addressing (element offsets within a tile)
    // A x4: row = mbase + (lane&15), k = (lane>>4)*8
    const int a_r = lane & 15, a_k = (lane >> 4) << 3;
    // B x4: row = nbase + (lane&7) + (lane>=16 ? 8:0), k = ((lane>>3)&1)*8
    const int b_r = (lane & 7) + ((lane >> 4) << 3), b_k = ((lane >> 3) & 1) << 3;

    auto load_tile = [&](int kt, int st) {
        const size_t k0 = (size_t)kt * BK;
        uint32_t da = sAb + (uint32_t)st * TILE_E * 2;
        uint32_t db = sBb + (uint32_t)st * TILE_E * 2;
        cp16(da + (c0r * LDS_ + c0k) * 2, A  + (size_t)(bm + c0r) * K3 + k0 + c0k);
        cp16(da + (c1r * LDS_ + c1k) * 2, A  + (size_t)(bm + c1r) * K3 + k0 + c1k);
        cp16(db + (c0r * LDS_ + c0k) * 2, Bm + (size_t)(bn + c0r) * K3 + k0 + c0k);
        cp16(db + (c1r * LDS_ + c1k) * 2, Bm + (size_t)(bn + c1r) * K3 + k0 + c1k);
        asm volatile("cp.async.commit_group;" ::: "memory");
    };

    load_tile(0, 0);

    for (int kt = 0; kt < NKT; kt++) {
        const int st = kt & 1;
        if (kt + 1 < NKT) {
            load_tile(kt + 1, st ^ 1);
            asm volatile("cp.async.wait_group 1;" ::: "memory");
        } else {
            asm volatile("cp.async.wait_group 0;" ::: "memory");
        }
        __syncthreads();

        const uint32_t da = sAb + (uint32_t)st * TILE_E * 2;
        const uint32_t db = sBb + (uint32_t)st * TILE_E * 2;

        #pragma unroll
        for (int ks = 0; ks < BK / 16; ks++) {
            // a-frags: 4 x ldmatrix.x4
            uint32_t af[4][4];
            #pragma unroll
            for (int mi = 0; mi < 4; mi++) {
                int row = wm + mi * 16 + a_r;
                ldm_x4(af[mi], da + (uint32_t)(row * LDS_ + ks * 16 + a_k) * 2);
            }
            // b-frags: 2 x ldmatrix.x4 (each covers 2 n-frags, both k halves)
            uint32_t bf[4][2];
            #pragma unroll
            for (int p = 0; p < 2; p++) {
                uint32_t r[4];
                int row = wn + p * 16 + b_r;
                ldm_x4(r, db + (uint32_t)(row * LDS_ + ks * 16 + b_k) * 2);
                bf[p * 2 + 0][0] = r[0]; bf[p * 2 + 0][1] = r[1];
                bf[p * 2 + 1][0] = r[2]; bf[p * 2 + 1][1] = r[3];
            }
            #pragma unroll
            for (int mi = 0; mi < 4; mi++)
                #pragma unroll
                for (int nj = 0; nj < 4; nj++)
                    mma16816(acc[mi][nj], af[mi], bf[nj]);
        }
        __syncthreads();
    }

    // epilogue: c-frag mapping: rows t/4 (+8), cols (t%4)*2
    const int er = lane >> 2, ec = (lane & 3) * 2;
    #pragma unroll
    for (int mi = 0; mi < 4; mi++) {
        #pragma unroll
        for (int nj = 0; nj < 4; nj++) {
            size_t row0 = (size_t)(bm + wm + mi * 16 + er);
            size_t col  = (size_t)(bn + wn + nj * 8 + ec);
            float2 v0 = make_float2(acc[mi][nj][0], acc[mi][nj][1]);
            float2 v1 = make_float2(acc[mi][nj][2], acc[mi][nj][3]);
            *(float2*)(C + row0 * N + col)       = v0;
            *(float2*)(C + (row0 + 8) * N + col) = v1;
        }
    }
}

// ---------------------------------------------------------------------------
// bf16 split helper
// ---------------------------------------------------------------------------
__device__ __forceinline__ void split2(float x, __nv_bfloat16& h, __nv_bfloat16& l) {
    h = __float2bfloat16(x);
    l = __float2bfloat16(x - __bfloat162float(h));
}

// 1) token mix + split -> g_A2 = [ah | al | ah]
__global__ void mix_split_kernel(const float* __restrict__ hsrc,
                                 const float* __restrict__ tm) {
    int i2 = blockIdx.x * blockDim.x + threadIdx.x;
    if (i2 >= M_ * HID_ / 2) return;
    int e = i2 * 2;
    int col = e & (HID_ - 1);
    int row = e >> 10;
    int s = row & (S_ - 1);
    float2 hv = *(const float2*)(hsrc + e);
    float2 tv = *(const float2*)(tm + col);
    float2 pv = make_float2(0.f, 0.f);
    if (s) pv = *(const float2*)(hsrc + e - HID_);
    float m0 = hv.x * tv.x + pv.x * (1.f - tv.x);
    float m1 = hv.y * tv.y + pv.y * (1.f - tv.y);
    __nv_bfloat16 h0, l0, h1, l1;
    split2(m0, h0, l0); split2(m1, h1, l1);
    __nv_bfloat162 Hh; Hh.x = h0; Hh.y = h1;
    __nv_bfloat162 Ll; Ll.x = l0; Ll.y = l1;
    __nv_bfloat16* base = g_A2 + (size_t)row * K3 + col;
    *(__nv_bfloat162*)(base)        = Hh;
    *(__nv_bfloat162*)(base + 1024) = Ll;
    *(__nv_bfloat162*)(base + 2048) = Hh;
}

// weight split -> out = [bh | bh | bl]
__global__ void wsplit_kernel(const float* __restrict__ W,
                              __nv_bfloat16* __restrict__ out, int rows) {
    int i2 = blockIdx.x * blockDim.x + threadIdx.x;
    if (i2 >= rows * (HID_ / 2)) return;
    int e = i2 * 2;
    int col = e & (HID_ - 1);
    int row = e >> 10;
    float2 w = *(const float2*)(W + e);
    __nv_bfloat16 h0, l0, h1, l1;
    split2(w.x, h0, l0); split2(w.y, h1, l1);
    __nv_bfloat162 Hh; Hh.x = h0; Hh.y = h1;
    __nv_bfloat162 Ll; Ll.x = l0; Ll.y = l1;
    __nv_bfloat16* base = out + (size_t)row * K3 + col;
    *(__nv_bfloat162*)(base)        = Hh;
    *(__nv_bfloat162*)(base + 1024) = Hh;
    *(__nv_bfloat162*)(base + 2048) = Ll;
}

// 3) sigmoid + RoPE + kv = k*v
__global__ void rope_kv_kernel(const float* __restrict__ cosb,
                               const float* __restrict__ sinb) {
    int idx = blockIdx.x * blockDim.x + threadIdx.x;
    if (idx >= M_ * HID_) return;
    int d  = idx & 63;
    int hd = idx & (HID_ - 1);
    int bs = idx >> 10;
    int s  = bs & (S_ - 1);
    const float* base = g_rkv + (size_t)bs * N1_;
    int pd = hd ^ 32;

    float rv  = base[hd];
    float rpv = base[pd];
    float kv  = base[1024 + hd];
    float kpv = base[1024 + pd];
    float vv  = base[2048 + hd];

    float c  = cosb[s * 64 + d];
    float sn = sinb[s * 64 + d];
    float sign = (d < 32) ? -1.f : 1.f;

    float rs  = 1.f / (1.f + __expf(-rv));
    float rps = 1.f / (1.f + __expf(-rpv));
    float rr  = rs * c + sign * rps * sn;
    float kk  = kv * c + sign * kpv * sn;

    g_r[idx]  = rr;
    g_kv[idx] = kk * vv;
}

// 4) scalar decay factor: a = mean(exp(td)), g = exp(a)
__global__ void prep_kernel(const float* __restrict__ td) {
    __shared__ float red[256];
    float s = 0.f;
    for (int i = threadIdx.x; i < H_ * D_; i += 256) s += expf(td[i]);
    red[threadIdx.x] = s;
    __syncthreads();
    for (int w = 128; w > 0; w >>= 1) {
        if (threadIdx.x < w) red[threadIdx.x] += red[threadIdx.x + w];
        __syncthreads();
    }
    if (threadIdx.x == 0) {
        float a = red[0] / (float)(H_ * D_);
        g_apos = a;
        g_gfac = expf(a);
    }
}

// 5a) local suffix scans over 64-element chunks
__global__ void scanA_kernel() {
    int gid = blockIdx.x * blockDim.x + threadIdx.x;   // B_*64*HID_ = 131072
    int ch = gid & (HID_ - 1);
    int c  = (gid >> 10) & 63;
    int b  = gid >> 16;
    float g = g_gfac;
    size_t base = ((size_t)(b * S_ + c * 64)) * HID_ + ch;
    float u = 0.f;
    #pragma unroll 4
    for (int p = 63; p >= 0; p--) {
        size_t idx = base + (size_t)p * HID_;
        u = fmaf(g, u, g_kv[idx]);
        g_uloc[idx] = u;
    }
    g_T[gid] = u;
}

// 5b) chunk-carry suffix combine (per channel)
__global__ void scanB_kernel() {
    int t = blockIdx.x * blockDim.x + threadIdx.x;     // B_*HID_ = 2048
    if (t >= B_ * HID_) return;
    int ch = t & (HID_ - 1);
    int b  = t >> 10;
    float gL = expf(g_apos * 64.f);
    float usuf = 0.f;
    for (int c = 63; c >= 0; c--) {
        int i = (b * 64 + c) * HID_ + ch;
        g_carry[i] = usuf;
        usuf = fmaf(gL, usuf, g_T[i]);
    }
}

// 5c) finalize: U = uloc + g^(64-p)*carry, den closed-form, gate, split -> g_A2
__global__ void scanC_kernel(const float* __restrict__ tf) {
    int idx = blockIdx.x * blockDim.x + threadIdx.x;   // M_*HID_
    if (idx >= M_ * HID_) return;
    int ch = idx & (HID_ - 1);
    int s  = (idx >> 10) & (S_ - 1);
    int b  = idx >> 22;
    int p  = s & 63;
    int c  = s >> 6;
    float a = g_apos;
    float carry = g_carry[(b * 64 + c) * HID_ + ch];
    float U = g_uloc[idx] + expf(a * (float)(64 - p)) * carry;
    float den = expm1f(a * (float)(S_ - s)) / expm1f(a);
    float wkv = U / (den + 1e-8f);
    float att = g_r[idx] * (tf[ch] * g_kv[idx] + wkv);
    __nv_bfloat16 h, l;
    split2(att, h, l);
    int row = idx >> 10;
    __nv_bfloat16* base = g_A2 + (size_t)row * K3 + ch;
    base[0]    = h;
    base[1024] = l;
    base[2048] = h;
}

// ---------------------------------------------------------------------------
// launch
// ---------------------------------------------------------------------------
extern "C" void kernel_launch(void* const* d_in, const int* in_sizes, int n_in,
                              void* d_out, int out_size) {
    const float* hidden = (const float*)d_in[0];
    const float* cosb   = (const float*)d_in[1];
    const float* sinb   = (const float*)d_in[2];
    const float* W_rkv  = (const float*)d_in[3];
    const float* W_o    = (const float*)d_in[4];
    const float* tdec   = (const float*)d_in[5];
    const float* tfirst = (const float*)d_in[6];
    const float* tmix   = (const float*)d_in[7];
    float* out = (float*)d_out;

    __nv_bfloat16 *A2, *B2rkv, *B2o;
    float *rkv;
    cudaGetSymbolAddress((void**)&A2,    g_A2);
    cudaGetSymbolAddress((void**)&B2rkv, g_B2rkv);
    cudaGetSymbolAddress((void**)&B2o,   g_B2o);
    cudaGetSymbolAddress((void**)&rkv,   g_rkv);

    // scalar decay factor (independent)
    prep_kernel<<<1, 256>>>(tdec);

    // token mix + split
    mix_split_kernel<<<(M_ * HID_ / 2 + 255) / 256, 256>>>(hidden, tmix);

    // weight splits
    wsplit_kernel<<<(N1_ * HID_ / 2 + 255) / 256, 256>>>(W_rkv, B2rkv, N1_);
    wsplit_kernel<<<(N2_ * HID_ / 2 + 255) / 256, 256>>>(W_o,   B2o,   N2_);

    // GEMM1: rkv = mixed @ W_rkv^T  (HMMA, split-bf16)
    gemm_hmma<<<dim3(N1_ / 128, M_ / 128), 256>>>(A2, B2rkv, rkv, N1_);

    // sigmoid + rope + kv
    rope_kv_kernel<<<(M_ * HID_ + 255) / 256, 256>>>(cosb, sinb);

    // chunked scan
    scanA_kernel<<<(B_ * 64 * HID_) / 256, 256>>>();
    scanB_kernel<<<(B_ * HID_ + 255) / 256, 256>>>();
    scanC_kernel<<<(M_ * HID_ + 255) / 256, 256>>>(tfirst);

    // GEMM2: out = att @ W_o^T  (HMMA, split-bf16)
    gemm_hmma<<<dim3(N2_ / 128, M_ / 128), 256>>>(A2, B2o, out, N2_);
}

// round 9
// speedup vs baseline: 6.7824x; 1.1512x over previous
#include <cuda_runtime.h>
#include <cuda_bf16.h>
#include <stdint.h>
#include <math.h>

// Problem constants
#define B_   2
#define S_   4096
#define HID_ 1024
#define H_   16
#define D_   64
#define M_   (B_*S_)        // 8192
#define N1_  (3*H_*D_)      // 3072
#define N2_  HID_           // 1024
#define K3   3072           // split-K': [ah|al|ah] x [bh|bh|bl]

// ---------------------------------------------------------------------------
// Scratch (no cudaMalloc allowed)
// ---------------------------------------------------------------------------
__device__ __align__(256) __nv_bfloat16 g_A2[(size_t)M_*K3];      // 50.3 MB
__device__ __align__(256) __nv_bfloat16 g_B2rkv[(size_t)N1_*K3];  // 18.9 MB
__device__ __align__(256) __nv_bfloat16 g_B2o[(size_t)N2_*K3];    //  6.3 MB
__device__ __align__(256) float g_rkv[(size_t)M_*N1_];            // 100.7 MB
__device__ __align__(256) float g_r[(size_t)M_*HID_];             //  33.5 MB
__device__ __align__(256) float g_kv[(size_t)M_*HID_];            //  33.5 MB
__device__ __align__(256) float g_uloc[(size_t)M_*HID_];          //  33.5 MB
__device__ __align__(256) float g_T[(size_t)B_*64*HID_];          //   0.5 MB
__device__ __align__(256) float g_carry[(size_t)B_*64*HID_];      //   0.5 MB
__device__ float g_gfac;   // exp(a)
__device__ float g_apos;   // a = mean(exp(time_decay)) = -avg_decay

// ---------------------------------------------------------------------------
// helpers
// ---------------------------------------------------------------------------
__device__ __forceinline__ uint32_t smem_u32(const void* p) {
    uint32_t a;
    asm("{ .reg .u64 t; cvta.to.shared.u64 t, %1; cvt.u32.u64 %0, t; }" : "=r"(a) : "l"(p));
    return a;
}
__device__ __forceinline__ void cp16(uint32_t dst, const void* src) {
    asm volatile("cp.async.cg.shared.global [%0], [%1], 16;" :: "r"(dst), "l"(src));
}
__device__ __forceinline__ void ldm_x4(uint32_t* r, uint32_t addr) {
    asm volatile("ldmatrix.sync.aligned.m8n8.x4.shared.b16 {%0,%1,%2,%3}, [%4];"
                 : "=r"(r[0]), "=r"(r[1]), "=r"(r[2]), "=r"(r[3]) : "r"(addr));
}
__device__ __forceinline__ void mma16816(float* c, const uint32_t* a, const uint32_t* b) {
    asm volatile(
        "mma.sync.aligned.m16n8k16.row.col.f32.bf16.bf16.f32 "
        "{%0,%1,%2,%3}, {%4,%5,%6,%7}, {%8,%9}, {%0,%1,%2,%3};"
        : "+f"(c[0]), "+f"(c[1]), "+f"(c[2]), "+f"(c[3])
        : "r"(a[0]), "r"(a[1]), "r"(a[2]), "r"(a[3]), "r"(b[0]), "r"(b[1]));
}

// ---------------------------------------------------------------------------
// bf16 HMMA GEMM: C[M,N] = A[M,K3] * B[N,K3]^T, fp32 out.
// CTA tile 128x128, BK=64, 3-stage cp.async ring, ONE sync per K-tile.
// 8 warps, 64x32 per warp (4 m-frags x 4 n-frags of m16n8k16).
// smem rows padded to 72 elems (144B stride -> mod-128B offsets 0,16,..112:
// conflict-free for ldmatrix and for cp.async 16B stores).
// ---------------------------------------------------------------------------
#define BK 64
#define NKT (K3/BK)            // 48
#define NSTG 3
#define LDS_ (BK + 8)          // 72
#define TILE_E (128*LDS_)      // 9216 elems = 18432 B
#define STG_B (2*TILE_E*2)     // A+B per stage = 36864 B
#define SMEM_DYN (NSTG*STG_B)  // 110592 B

__global__ void __launch_bounds__(256, 2)
gemm_hmma(const __nv_bfloat16* __restrict__ A,
          const __nv_bfloat16* __restrict__ Bm,
          float* __restrict__ C, int N) {
    extern __shared__ __nv_bfloat16 smem[];
    const uint32_t sb = smem_u32(smem);

    const int tid = threadIdx.x;
    const int wid = tid >> 5, lane = tid & 31;
    const int bm = blockIdx.y * 128;
    const int bn = blockIdx.x * 128;
    const int wm = (wid & 1) * 64;
    const int wn = (wid >> 1) * 32;

    // cp.async: 1024 16B-chunks per matrix per tile, 4 per thread
    // chunk c: row = c>>3, k = (c&7)*8
    float acc[4][4][4];
    #pragma unroll
    for (int i = 0; i < 4; i++)
        #pragma unroll
        for (int j = 0; j < 4; j++)
            #pragma unroll
            for (int q = 0; q < 4; q++) acc[i][j][q] = 0.f;

    // ldmatrix lane addressing (element offsets within tile)
    const int a_r = lane & 15, a_k = (lane >> 4) << 3;
    const int b_r = (lane & 7) + ((lane >> 4) << 3), b_k = ((lane >> 3) & 1) << 3;

    auto load_tile = [&](int kt, int st) {
        const size_t k0 = (size_t)kt * BK;
        uint32_t da = sb + (uint32_t)st * STG_B;
        uint32_t db = da + TILE_E * 2;
        #pragma unroll
        for (int j = 0; j < 4; j++) {
            int c = tid + j * 256;
            int r = c >> 3, k = (c & 7) * 8;
            uint32_t so = (uint32_t)(r * LDS_ + k) * 2;
            cp16(da + so, A  + (size_t)(bm + r) * K3 + k0 + k);
            cp16(db + so, Bm + (size_t)(bn + r) * K3 + k0 + k);
        }
        asm volatile("cp.async.commit_group;" ::: "memory");
    };

    load_tile(0, 0);
    load_tile(1, 1);

    for (int kt = 0; kt < NKT; kt++) {
        const int st = kt % NSTG;
        if (kt < NKT - 1) asm volatile("cp.async.wait_group 1;" ::: "memory");
        else              asm volatile("cp.async.wait_group 0;" ::: "memory");
        __syncthreads();

        const int nt = kt + NSTG - 1;
        if (nt < NKT) load_tile(nt, nt % NSTG);

        const uint32_t da = sb + (uint32_t)st * STG_B;
        const uint32_t db = da + TILE_E * 2;

        #pragma unroll
        for (int ks = 0; ks < BK / 16; ks++) {
            uint32_t af[4][4];
            #pragma unroll
            for (int mi = 0; mi < 4; mi++) {
                int row = wm + mi * 16 + a_r;
                ldm_x4(af[mi], da + (uint32_t)(row * LDS_ + ks * 16 + a_k) * 2);
            }
            uint32_t bf[4][2];
            #pragma unroll
            for (int p = 0; p < 2; p++) {
                uint32_t r[4];
                int row = wn + p * 16 + b_r;
                ldm_x4(r, db + (uint32_t)(row * LDS_ + ks * 16 + b_k) * 2);
                bf[p * 2 + 0][0] = r[0]; bf[p * 2 + 0][1] = r[1];
                bf[p * 2 + 1][0] = r[2]; bf[p * 2 + 1][1] = r[3];
            }
            #pragma unroll
            for (int mi = 0; mi < 4; mi++)
                #pragma unroll
                for (int nj = 0; nj < 4; nj++)
                    mma16816(acc[mi][nj], af[mi], bf[nj]);
        }
    }

    // epilogue
    const int er = lane >> 2, ec = (lane & 3) * 2;
    #pragma unroll
    for (int mi = 0; mi < 4; mi++) {
        #pragma unroll
        for (int nj = 0; nj < 4; nj++) {
            size_t row0 = (size_t)(bm + wm + mi * 16 + er);
            size_t col  = (size_t)(bn + wn + nj * 8 + ec);
            float2 v0 = make_float2(acc[mi][nj][0], acc[mi][nj][1]);
            float2 v1 = make_float2(acc[mi][nj][2], acc[mi][nj][3]);
            *(float2*)(C + row0 * N + col)       = v0;
            *(float2*)(C + (row0 + 8) * N + col) = v1;
        }
    }
}

// ---------------------------------------------------------------------------
// bf16 split helper
// ---------------------------------------------------------------------------
__device__ __forceinline__ void split2(float x, __nv_bfloat16& h, __nv_bfloat16& l) {
    h = __float2bfloat16(x);
    l = __float2bfloat16(x - __bfloat162float(h));
}

// 1) token mix + split -> g_A2 = [ah | al | ah]
__global__ void mix_split_kernel(const float* __restrict__ hsrc,
                                 const float* __restrict__ tm) {
    int i2 = blockIdx.x * blockDim.x + threadIdx.x;
    if (i2 >= M_ * HID_ / 2) return;
    int e = i2 * 2;
    int col = e & (HID_ - 1);
    int row = e >> 10;
    int s = row & (S_ - 1);
    float2 hv = *(const float2*)(hsrc + e);
    float2 tv = *(const float2*)(tm + col);
    float2 pv = make_float2(0.f, 0.f);
    if (s) pv = *(const float2*)(hsrc + e - HID_);
    float m0 = hv.x * tv.x + pv.x * (1.f - tv.x);
    float m1 = hv.y * tv.y + pv.y * (1.f - tv.y);
    __nv_bfloat16 h0, l0, h1, l1;
    split2(m0, h0, l0); split2(m1, h1, l1);
    __nv_bfloat162 Hh; Hh.x = h0; Hh.y = h1;
    __nv_bfloat162 Ll; Ll.x = l0; Ll.y = l1;
    __nv_bfloat16* base = g_A2 + (size_t)row * K3 + col;
    *(__nv_bfloat162*)(base)        = Hh;
    *(__nv_bfloat162*)(base + 1024) = Ll;
    *(__nv_bfloat162*)(base + 2048) = Hh;
}

// weight split -> out = [bh | bh | bl]
__global__ void wsplit_kernel(const float* __restrict__ W,
                              __nv_bfloat16* __restrict__ out, int rows) {
    int i2 = blockIdx.x * blockDim.x + threadIdx.x;
    if (i2 >= rows * (HID_ / 2)) return;
    int e = i2 * 2;
    int col = e & (HID_ - 1);
    int row = e >> 10;
    float2 w = *(const float2*)(W + e);
    __nv_bfloat16 h0, l0, h1, l1;
    split2(w.x, h0, l0); split2(w.y, h1, l1);
    __nv_bfloat162 Hh; Hh.x = h0; Hh.y = h1;
    __nv_bfloat162 Ll; Ll.x = l0; Ll.y = l1;
    __nv_bfloat16* base = out + (size_t)row * K3 + col;
    *(__nv_bfloat162*)(base)        = Hh;
    *(__nv_bfloat162*)(base + 1024) = Hh;
    *(__nv_bfloat162*)(base + 2048) = Ll;
}

// 4) scalar decay factor: a = mean(exp(td)), g = exp(a)
__global__ void prep_kernel(const float* __restrict__ td) {
    __shared__ float red[256];
    float s = 0.f;
    for (int i = threadIdx.x; i < H_ * D_; i += 256) s += expf(td[i]);
    red[threadIdx.x] = s;
    __syncthreads();
    for (int w = 128; w > 0; w >>= 1) {
        if (threadIdx.x < w) red[threadIdx.x] += red[threadIdx.x + w];
        __syncthreads();
    }
    if (threadIdx.x == 0) {
        float a = red[0] / (float)(H_ * D_);
        g_apos = a;
        g_gfac = expf(a);
    }
}

// 5a) FUSED: sigmoid + RoPE + kv=k*v + local suffix scan over 64-chunks
__global__ void scanA_kernel(const float* __restrict__ cosb,
                             const float* __restrict__ sinb) {
    int gid = blockIdx.x * blockDim.x + threadIdx.x;   // B_*64*HID_ = 131072
    int ch = gid & (HID_ - 1);
    int c  = (gid >> 10) & 63;
    int b  = gid >> 16;
    int d  = ch & 63;
    int pd = ch ^ 32;
    float sign = (d < 32) ? -1.f : 1.f;
    float g = g_gfac;

    float u = 0.f;
    #pragma unroll 2
    for (int p = 63; p >= 0; p--) {
        int s = c * 64 + p;
        size_t row = (size_t)b * S_ + s;
        const float* base = g_rkv + row * N1_;

        float rv  = base[ch];
        float rpv = base[pd];
        float kvv = base[1024 + ch];
        float kpv = base[1024 + pd];
        float vv  = base[2048 + ch];

        float cc = cosb[s * 64 + d];
        float sn = sinb[s * 64 + d];

        float rs  = 1.f / (1.f + __expf(-rv));
        float rps = 1.f / (1.f + __expf(-rpv));
        float rr  = rs * cc + sign * rps * sn;
        float kk  = kvv * cc + sign * kpv * sn;
        float kvp = kk * vv;

        size_t idx = row * HID_ + ch;
        g_r[idx]  = rr;
        g_kv[idx] = kvp;
        u = fmaf(g, u, kvp);
        g_uloc[idx] = u;
    }
    g_T[gid] = u;
}

// 5b) chunk-carry suffix combine (per channel)
__global__ void scanB_kernel() {
    int t = blockIdx.x * blockDim.x + threadIdx.x;     // B_*HID_ = 2048
    if (t >= B_ * HID_) return;
    int ch = t & (HID_ - 1);
    int b  = t >> 10;
    float gL = expf(g_apos * 64.f);
    float usuf = 0.f;
    for (int c = 63; c >= 0; c--) {
        int i = (b * 64 + c) * HID_ + ch;
        g_carry[i] = usuf;
        usuf = fmaf(gL, usuf, g_T[i]);
    }
}

// 5c) finalize: U = uloc + g^(64-p)*carry, den closed-form, gate, split -> g_A2
__global__ void scanC_kernel(const float* __restrict__ tf) {
    int idx = blockIdx.x * blockDim.x + threadIdx.x;   // M_*HID_
    if (idx >= M_ * HID_) return;
    int ch = idx & (HID_ - 1);
    int s  = (idx >> 10) & (S_ - 1);
    int b  = idx >> 22;
    int p  = s & 63;
    int c  = s >> 6;
    float a = g_apos;
    float carry = g_carry[(b * 64 + c) * HID_ + ch];
    float U = g_uloc[idx] + expf(a * (float)(64 - p)) * carry;
    float den = expm1f(a * (float)(S_ - s)) / expm1f(a);
    float wkv = U / (den + 1e-8f);
    float att = g_r[idx] * (tf[ch] * g_kv[idx] + wkv);
    __nv_bfloat16 h, l;
    split2(att, h, l);
    int row = idx >> 10;
    __nv_bfloat16* base = g_A2 + (size_t)row * K3 + ch;
    base[0]    = h;
    base[1024] = l;
    base[2048] = h;
}

// ---------------------------------------------------------------------------
// launch
// ---------------------------------------------------------------------------
extern "C" void kernel_launch(void* const* d_in, const int* in_sizes, int n_in,
                              void* d_out, int out_size) {
    const float* hidden = (const float*)d_in[0];
    const float* cosb   = (const float*)d_in[1];
    const float* sinb   = (const float*)d_in[2];
    const float* W_rkv  = (const float*)d_in[3];
    const float* W_o    = (const float*)d_in[4];
    const float* tdec   = (const float*)d_in[5];
    const float* tfirst = (const float*)d_in[6];
    const float* tmix   = (const float*)d_in[7];
    float* out = (float*)d_out;

    __nv_bfloat16 *A2, *B2rkv, *B2o;
    float *rkv;
    cudaGetSymbolAddress((void**)&A2,    g_A2);
    cudaGetSymbolAddress((void**)&B2rkv, g_B2rkv);
    cudaGetSymbolAddress((void**)&B2o,   g_B2o);
    cudaGetSymbolAddress((void**)&rkv,   g_rkv);

    cudaFuncSetAttribute(gemm_hmma,
                         cudaFuncAttributeMaxDynamicSharedMemorySize, SMEM_DYN);

    // scalar decay factor (independent)
    prep_kernel<<<1, 256>>>(tdec);

    // token mix + split
    mix_split_kernel<<<(M_ * HID_ / 2 + 255) / 256, 256>>>(hidden, tmix);

    // weight splits
    wsplit_kernel<<<(N1_ * HID_ / 2 + 255) / 256, 256>>>(W_rkv, B2rkv, N1_);
    wsplit_kernel<<<(N2_ * HID_ / 2 + 255) / 256, 256>>>(W_o,   B2o,   N2_);

    // GEMM1: rkv = mixed @ W_rkv^T  (HMMA, split-bf16)
    gemm_hmma<<<dim3(N1_ / 128, M_ / 128), 256, SMEM_DYN>>>(A2, B2rkv, rkv, N1_);

    // fused rope/sigmoid/kv + local scan
    scanA_kernel<<<(B_ * 64 * HID_) / 256, 256>>>(cosb, sinb);
    scanB_kernel<<<(B_ * HID_ + 255) / 256, 256>>>();
    scanC_kernel<<<(M_ * HID_ + 255) / 256, 256>>>(tfirst);

    // GEMM2: out = att @ W_o^T  (HMMA, split-bf16)
    gemm_hmma<<<dim3(N2_ / 128, M_ / 128), 256, SMEM_DYN>>>(A2, B2o, out, N2_);
}